// round 9
// baseline (speedup 1.0000x reference)
#include <cuda_runtime.h>
#include <cstdint>

// ---------------- Single fused kernel ----------------
// out[t,k] = sum_a x[t,a] * M[k,a]
// M[k,a]   = sum_ij ( P_re[i,j] A_real[k,i,j,a] - P_im[i,j] A_imag[k,i,j,a] )
#define WARPS_PB   8
#define BLOCK_T    256
#define ROWS_W     32                          // rows per warp-stage chunk
#define F4_W       (ROWS_W * 25)               // 800 float4 per stage
#define STAGES     2
#define SMEM_BYTES (WARPS_PB * STAGES * F4_W * 16)   // 204800 B -> 1 block/SM

__device__ __forceinline__ void mbar_wait(unsigned mbar, unsigned phase) {
    unsigned done;
    asm volatile("{\n\t.reg .pred p;\n\t"
                 "mbarrier.try_wait.parity.acquire.cta.shared::cta.b64 p, [%1], %2;\n\t"
                 "selp.b32 %0, 1, 0, p;\n\t}"
                 : "=r"(done) : "r"(mbar), "r"(phase) : "memory");
    while (!done) {
        asm volatile("{\n\t.reg .pred p;\n\t"
                     "mbarrier.try_wait.parity.acquire.cta.shared::cta.b64 p, [%1], %2, 0x989680;\n\t"
                     "selp.b32 %0, 1, 0, p;\n\t}"
                     : "=r"(done) : "r"(mbar), "r"(phase) : "memory");
    }
}

__global__ void __launch_bounds__(BLOCK_T, 1) fused_kernel(
    const float* __restrict__ x,
    const float* __restrict__ A_real,
    const float* __restrict__ A_imag,
    const float* __restrict__ psi_real,
    const float* __restrict__ psi_imag,
    float2* __restrict__ out,
    int batch, int nchunks)
{
    extern __shared__ __align__(128) float4 sx[];   // [WARPS_PB][STAGES][F4_W]
    __shared__ __align__(16) float sMf[200];
    __shared__ float sPre[100], sPim[100];
    __shared__ float sI0[100], sI1[100];            // imag-part partials per a
    __shared__ __align__(8) unsigned long long mbar_store[WARPS_PB * STAGES];

    int tid  = threadIdx.x;
    int wid  = tid >> 5;
    int lane = tid & 31;

    unsigned mbar_base = (unsigned)__cvta_generic_to_shared(&mbar_store[0]);
    unsigned wmbar = mbar_base + (wid * STAGES) * 8;
    float4* ws = sx + (size_t)wid * (STAGES * F4_W);

    if (tid < WARPS_PB * STAGES)
        asm volatile("mbarrier.init.shared.b64 [%0], %1;"
                     :: "r"(mbar_base + tid * 8), "r"(1) : "memory");

    // Weight table: Pre[ij], Pim[ij].
    __shared__ float spr[10], spi[10];
    if (tid < 10) { spr[tid] = psi_real[tid]; spi[tid] = psi_imag[tid]; }
    __syncthreads();
    if (tid < 100) {
        int i = tid / 10, j = tid - i * 10;
        sPre[tid] = spr[i] * spr[j] + spi[i] * spi[j];
        sPim[tid] = spr[i] * spi[j] - spi[i] * spr[j];
    }

    int gwarp  = blockIdx.x * WARPS_PB + wid;
    int stride = gridDim.x * WARPS_PB;

    // Issue one 32-row chunk into warp-stage s (single bulk copy, lane 0).
    auto issue = [&](int chunk, int s) {
        if (lane == 0) {
            int rows = batch - chunk * ROWS_W;
            if (rows > ROWS_W) rows = ROWS_W;
            unsigned bytes = (unsigned)rows * 400u;
            unsigned mb = wmbar + s * 8;
            asm volatile("mbarrier.arrive.expect_tx.shared.b64 _, [%0], %1;"
                         :: "r"(mb), "r"(bytes) : "memory");
            unsigned dst = (unsigned)__cvta_generic_to_shared(ws + s * F4_W);
            const float* src = x + (size_t)chunk * (ROWS_W * 100);
            asm volatile("cp.async.bulk.shared::cta.global.mbarrier::complete_tx::bytes "
                         "[%0], [%1], %2, [%3];"
                         :: "r"(dst), "l"(src), "r"(bytes), "r"(mb) : "memory");
        }
    };

    // Prologue: enqueue both stages of every warp first (~205KB/SM in flight).
    if (gwarp < nchunks)          issue(gwarp, 0);
    if (gwarp + stride < nchunks) issue(gwarp + stride, 1);

    __syncthreads();   // sPre/sPim ready

    // Coalesced M compute, hidden under the TMA flight.
    // Thread t<100: real part for a=t (both k). Thread 100<=t<200: imag part.
    if (tid < 200) {
        int a    = (tid < 100) ? tid : tid - 100;
        bool im  = (tid >= 100);
        const float* A = im ? A_imag : A_real;
        const float* w = im ? sPim : sPre;
        float acc0 = 0.0f, acc1 = 0.0f;
        #pragma unroll 10
        for (int ij = 0; ij < 100; ij++) {
            float wv = w[ij];
            acc0 = fmaf(wv, __ldg(A + ij * 100 + a), acc0);
            acc1 = fmaf(wv, __ldg(A + 10000 + ij * 100 + a), acc1);
        }
        if (im) { sI0[a] = acc0; sI1[a] = acc1; }
        else    { sMf[a] = acc0; sMf[100 + a] = acc1; }   // real part staged
    }
    __syncthreads();
    if (tid < 100) {
        sMf[tid]       -= sI0[tid];
        sMf[100 + tid] -= sI1[tid];
    }
    __syncthreads();
    const float4* sM4 = reinterpret_cast<const float4*>(sMf);   // [50]

    // Steady loop (R7-identical): warp-private, no block barriers.
    int cnt = 0;
    for (int c = gwarp; c < nchunks; c += stride, cnt++) {
        int s = cnt & 1;
        unsigned phase = (cnt >> 1) & 1;
        mbar_wait(wmbar + s * 8, phase);

        int row = c * ROWS_W + lane;
        const float4* xr = ws + s * F4_W + lane * 25;
        float s0 = 0.0f, s1 = 0.0f;
        #pragma unroll
        for (int i = 0; i < 25; i++) {
            float4 v  = xr[i];
            float4 m0 = sM4[i];
            float4 m1 = sM4[25 + i];
            s0 = fmaf(v.x, m0.x, s0); s0 = fmaf(v.y, m0.y, s0);
            s0 = fmaf(v.z, m0.z, s0); s0 = fmaf(v.w, m0.w, s0);
            s1 = fmaf(v.x, m1.x, s1); s1 = fmaf(v.y, m1.y, s1);
            s1 = fmaf(v.z, m1.z, s1); s1 = fmaf(v.w, m1.w, s1);
        }
        if (row < batch) out[row] = make_float2(s0, s1);
        __syncwarp();                      // whole warp done reading stage s

        int cn = c + STAGES * stride;
        if (cn < nchunks) issue(cn, s);
    }
}

extern "C" void kernel_launch(void* const* d_in, const int* in_sizes, int n_in,
                              void* d_out, int out_size) {
    const float* x        = (const float*)d_in[0];  // [BATCH, 100]
    const float* A_real   = (const float*)d_in[1];  // [2,10,10,100]
    const float* A_imag   = (const float*)d_in[2];  // [2,10,10,100]
    const float* psi_real = (const float*)d_in[3];  // [10]
    const float* psi_imag = (const float*)d_in[4];  // [10]

    int batch   = in_sizes[0] / 100;
    int nchunks = (batch + ROWS_W - 1) / ROWS_W;

    static bool attr_done = false;
    if (!attr_done) {
        cudaFuncSetAttribute(fused_kernel,
                             cudaFuncAttributeMaxDynamicSharedMemorySize, SMEM_BYTES);
        attr_done = true;
    }

    fused_kernel<<<148, BLOCK_T, SMEM_BYTES>>>(x, A_real, A_imag,
                                               psi_real, psi_imag,
                                               reinterpret_cast<float2*>(d_out),
                                               batch, nchunks);
}

// round 10
// speedup vs baseline: 1.0483x; 1.0483x over previous
#include <cuda_runtime.h>
#include <cstdint>

// ---------------- Single fused kernel ----------------
// out[t,k] = sum_a x[t,a] * M[k,a]
// M[k,a]   = sum_ij ( P_re[i,j] A_real[k,i,j,a] - P_im[i,j] A_imag[k,i,j,a] )
#define WARPS_PB   8
#define BLOCK_T    256
#define ROWS_W     32                          // rows per warp-stage chunk
#define F4_W       (ROWS_W * 25)               // 800 float4 per stage
#define STAGES     2
#define SMEM_BYTES (WARPS_PB * STAGES * F4_W * 16)   // 204800 B -> 1 block/SM

__device__ __forceinline__ void mbar_wait(unsigned mbar, unsigned phase) {
    unsigned done;
    asm volatile("{\n\t.reg .pred p;\n\t"
                 "mbarrier.try_wait.parity.acquire.cta.shared::cta.b64 p, [%1], %2;\n\t"
                 "selp.b32 %0, 1, 0, p;\n\t}"
                 : "=r"(done) : "r"(mbar), "r"(phase) : "memory");
    while (!done) {
        asm volatile("{\n\t.reg .pred p;\n\t"
                     "mbarrier.try_wait.parity.acquire.cta.shared::cta.b64 p, [%1], %2, 0x989680;\n\t"
                     "selp.b32 %0, 1, 0, p;\n\t}"
                     : "=r"(done) : "r"(mbar), "r"(phase) : "memory");
    }
}

__global__ void __launch_bounds__(BLOCK_T, 1) fused_kernel(
    const float* __restrict__ x,
    const float* __restrict__ A_real,
    const float* __restrict__ A_imag,
    const float* __restrict__ psi_real,
    const float* __restrict__ psi_imag,
    float2* __restrict__ out,
    int batch, int nchunks)
{
    extern __shared__ __align__(128) float4 sx[];   // [WARPS_PB][STAGES][F4_W]
    __shared__ __align__(16) float sMf[200];
    __shared__ float sPre[100], sPim[100];
    __shared__ float spr[10], spi[10];
    __shared__ __align__(8) unsigned long long mbar_store[WARPS_PB * STAGES];

    int tid  = threadIdx.x;
    int wid  = tid >> 5;
    int lane = tid & 31;

    unsigned mbar_base = (unsigned)__cvta_generic_to_shared(&mbar_store[0]);
    unsigned wmbar = mbar_base + (wid * STAGES) * 8;
    float4* ws = sx + (size_t)wid * (STAGES * F4_W);

    if (tid < WARPS_PB * STAGES)
        asm volatile("mbarrier.init.shared.b64 [%0], %1;"
                     :: "r"(mbar_base + tid * 8), "r"(1) : "memory");
    if (tid < 10) { spr[tid] = psi_real[tid]; spi[tid] = psi_imag[tid]; }
    __syncthreads();

    // Weight table + zero the accumulator (no sync needed until after issue).
    if (tid < 100) {
        int i = tid / 10, j = tid - i * 10;
        sPre[tid] = spr[i] * spr[j] + spi[i] * spi[j];
        sPim[tid] = spr[i] * spi[j] - spi[i] * spr[j];
    }
    if (tid < 200) sMf[tid] = 0.0f;

    int gwarp  = blockIdx.x * WARPS_PB + wid;
    int stride = gridDim.x * WARPS_PB;

    // Issue one 32-row chunk into warp-stage s (single bulk copy, lane 0).
    auto issue = [&](int chunk, int s) {
        if (lane == 0) {
            int rows = batch - chunk * ROWS_W;
            if (rows > ROWS_W) rows = ROWS_W;
            unsigned bytes = (unsigned)rows * 400u;
            unsigned mb = wmbar + s * 8;
            asm volatile("mbarrier.arrive.expect_tx.shared.b64 _, [%0], %1;"
                         :: "r"(mb), "r"(bytes) : "memory");
            unsigned dst = (unsigned)__cvta_generic_to_shared(ws + s * F4_W);
            const float* src = x + (size_t)chunk * (ROWS_W * 100);
            asm volatile("cp.async.bulk.shared::cta.global.mbarrier::complete_tx::bytes "
                         "[%0], [%1], %2, [%3];"
                         :: "r"(dst), "l"(src), "r"(bytes), "r"(mb) : "memory");
        }
    };

    // Prologue: enqueue both stages of every warp (~205KB/SM TMA in flight).
    if (gwarp < nchunks)          issue(gwarp, 0);
    if (gwarp + stride < nchunks) issue(gwarp + stride, 1);

    __syncthreads();   // weights + zeros visible

    // Latency-flat M compute: 2000 tasks (k,i,a), 8 per thread, all 160
    // loads independent -> single DRAM/L2 latency wave, hidden by TMA flight.
    {
        float acc[8];
        int   dst[8];
        #pragma unroll
        for (int r = 0; r < 8; r++) {
            int t = tid + r * BLOCK_T;          // 0..2047
            float a8 = 0.0f;
            int d = 0;
            if (t < 2000) {
                int a = t % 100;
                int g = t / 100;                // 0..19
                int i = g % 10;
                int k = g / 10;
                int base = ((k * 10 + i) * 10) * 100 + a;
                #pragma unroll
                for (int j = 0; j < 10; j++) {
                    float wr = sPre[i * 10 + j];
                    float wi = sPim[i * 10 + j];
                    a8 = fmaf(wr,  __ldg(A_real + base + j * 100), a8);
                    a8 = fmaf(-wi, __ldg(A_imag + base + j * 100), a8);
                }
                d = k * 100 + a;
            } else {
                d = -1;
            }
            acc[r] = a8;
            dst[r] = d;
        }
        #pragma unroll
        for (int r = 0; r < 8; r++)
            if (dst[r] >= 0) atomicAdd(&sMf[dst[r]], acc[r]);
    }
    __syncthreads();
    const float4* sM4 = reinterpret_cast<const float4*>(sMf);   // [50]

    // Steady loop (R7-identical): warp-private, no block barriers.
    int cnt = 0;
    for (int c = gwarp; c < nchunks; c += stride, cnt++) {
        int s = cnt & 1;
        unsigned phase = (cnt >> 1) & 1;
        mbar_wait(wmbar + s * 8, phase);

        int row = c * ROWS_W + lane;
        const float4* xr = ws + s * F4_W + lane * 25;
        float s0 = 0.0f, s1 = 0.0f;
        #pragma unroll
        for (int i = 0; i < 25; i++) {
            float4 v  = xr[i];
            float4 m0 = sM4[i];
            float4 m1 = sM4[25 + i];
            s0 = fmaf(v.x, m0.x, s0); s0 = fmaf(v.y, m0.y, s0);
            s0 = fmaf(v.z, m0.z, s0); s0 = fmaf(v.w, m0.w, s0);
            s1 = fmaf(v.x, m1.x, s1); s1 = fmaf(v.y, m1.y, s1);
            s1 = fmaf(v.z, m1.z, s1); s1 = fmaf(v.w, m1.w, s1);
        }
        if (row < batch) out[row] = make_float2(s0, s1);
        __syncwarp();                      // whole warp done reading stage s

        int cn = c + STAGES * stride;
        if (cn < nchunks) issue(cn, s);
    }
}

extern "C" void kernel_launch(void* const* d_in, const int* in_sizes, int n_in,
                              void* d_out, int out_size) {
    const float* x        = (const float*)d_in[0];  // [BATCH, 100]
    const float* A_real   = (const float*)d_in[1];  // [2,10,10,100]
    const float* A_imag   = (const float*)d_in[2];  // [2,10,10,100]
    const float* psi_real = (const float*)d_in[3];  // [10]
    const float* psi_imag = (const float*)d_in[4];  // [10]

    int batch   = in_sizes[0] / 100;
    int nchunks = (batch + ROWS_W - 1) / ROWS_W;

    static bool attr_done = false;
    if (!attr_done) {
        cudaFuncSetAttribute(fused_kernel,
                             cudaFuncAttributeMaxDynamicSharedMemorySize, SMEM_BYTES);
        attr_done = true;
    }

    fused_kernel<<<148, BLOCK_T, SMEM_BYTES>>>(x, A_real, A_imag,
                                               psi_real, psi_imag,
                                               reinterpret_cast<float2*>(d_out),
                                               batch, nchunks);
}

// round 11
// speedup vs baseline: 1.0739x; 1.0244x over previous
#include <cuda_runtime.h>
#include <cstdint>

#define WARPS_PB   8
#define BLOCK_T    256
#define ROWS_W     32                          // rows per warp-stage chunk
#define F4_W       (ROWS_W * 25)               // 800 float4 per stage
#define STAGES     2
#define SMEM_BYTES (WARPS_PB * STAGES * F4_W * 16)   // 204800 B -> 1 block/SM
#define NBLK       148

// Per-launch control block, zeroed by a cudaMemsetAsync graph node each launch.
struct Ctrl {
    int   counter;      // work-stealing chunk counter
    int   done;         // count of finished M-blocks (target 20)
    int   pad0, pad1;
    float M[200];       // M[k*100 + a]
};
__device__ __align__(16) Ctrl g_ctrl;

__device__ __forceinline__ void mbar_wait(unsigned mbar, unsigned phase) {
    unsigned done;
    asm volatile("{\n\t.reg .pred p;\n\t"
                 "mbarrier.try_wait.parity.acquire.cta.shared::cta.b64 p, [%1], %2;\n\t"
                 "selp.b32 %0, 1, 0, p;\n\t}"
                 : "=r"(done) : "r"(mbar), "r"(phase) : "memory");
    while (!done) {
        asm volatile("{\n\t.reg .pred p;\n\t"
                     "mbarrier.try_wait.parity.acquire.cta.shared::cta.b64 p, [%1], %2, 0x989680;\n\t"
                     "selp.b32 %0, 1, 0, p;\n\t}"
                     : "=r"(done) : "r"(mbar), "r"(phase) : "memory");
    }
}

__global__ void __launch_bounds__(BLOCK_T, 1) fused_kernel(
    const float* __restrict__ x,
    const float* __restrict__ A_real,
    const float* __restrict__ A_imag,
    const float* __restrict__ psi_real,
    const float* __restrict__ psi_imag,
    float2* __restrict__ out,
    int batch, int nchunks)
{
    extern __shared__ __align__(128) float4 sx[];   // [WARPS_PB][STAGES][F4_W]
    __shared__ __align__(16) float sMf[200];
    __shared__ float spr[10], spi[10];
    __shared__ __align__(8) unsigned long long mbar_store[WARPS_PB * STAGES];

    int tid  = threadIdx.x;
    int wid  = tid >> 5;
    int lane = tid & 31;
    int bid  = blockIdx.x;

    unsigned mbar_base = (unsigned)__cvta_generic_to_shared(&mbar_store[0]);
    unsigned wmbar = mbar_base + (wid * STAGES) * 8;
    float4* ws = sx + (size_t)wid * (STAGES * F4_W);

    if (tid < WARPS_PB * STAGES)
        asm volatile("mbarrier.init.shared.b64 [%0], %1;"
                     :: "r"(mbar_base + tid * 8), "r"(1) : "memory");
    if (bid < 20 && tid < 10) { spr[tid] = psi_real[tid]; spi[tid] = psi_imag[tid]; }
    __syncthreads();

    // Work-stealing: lane 0 grabs the next chunk id, broadcast to the warp.
    auto grab = [&]() -> int {
        int c = 0;
        if (lane == 0) c = atomicAdd(&g_ctrl.counter, 1);
        return __shfl_sync(0xffffffff, c, 0);
    };

    // Issue one 32-row chunk into warp-stage s (single bulk copy, lane 0).
    auto issue = [&](int chunk, int s) {
        if (lane == 0) {
            int rows = batch - chunk * ROWS_W;
            if (rows > ROWS_W) rows = ROWS_W;
            unsigned bytes = (unsigned)rows * 400u;
            unsigned mb = wmbar + s * 8;
            asm volatile("mbarrier.arrive.expect_tx.shared.b64 _, [%0], %1;"
                         :: "r"(mb), "r"(bytes) : "memory");
            unsigned dst = (unsigned)__cvta_generic_to_shared(ws + s * F4_W);
            const float* src = x + (size_t)chunk * (ROWS_W * 100);
            asm volatile("cp.async.bulk.shared::cta.global.mbarrier::complete_tx::bytes "
                         "[%0], [%1], %2, [%3];"
                         :: "r"(dst), "l"(src), "r"(bytes), "r"(mb) : "memory");
        }
    };

    // Prologue: every warp enqueues two chunks before anything else.
    int c0 = grab(); if (c0 < nchunks) issue(c0, 0);
    int c1 = grab(); if (c1 < nchunks) issue(c1, 1);

    // Blocks 0..19: compute the (k,i) partial of M (20 coalesced loads/thread),
    // hidden under the TMA flight. Total A traffic: 160KB once, not per-block.
    if (bid < 20 && tid < 100) {
        int k = bid / 10, i = bid - (bid / 10) * 10;
        int a = tid;
        int base = ((k * 10 + i) * 10) * 100 + a;
        float acc = 0.0f;
        #pragma unroll
        for (int j = 0; j < 10; j++) {
            float wr = spr[i] * spr[j] + spi[i] * spi[j];
            float wi = spr[i] * spi[j] - spi[i] * spr[j];
            acc = fmaf(wr,  __ldg(A_real + base + j * 100), acc);
            acc = fmaf(-wi, __ldg(A_imag + base + j * 100), acc);
        }
        atomicAdd(&g_ctrl.M[k * 100 + a], acc);
    }
    __syncthreads();
    if (bid < 20 && tid == 0) {
        __threadfence();
        atomicAdd(&g_ctrl.done, 1);
    }

    // All blocks: wait for M (covered by the in-flight prologue copies).
    if (tid == 0) {
        while (atomicAdd(&g_ctrl.done, 0) < 20) __nanosleep(64);
    }
    __syncthreads();
    __threadfence();
    if (tid < 200) sMf[tid] = __ldcg(&g_ctrl.M[tid]);   // bypass L1
    __syncthreads();
    const float4* sM4 = reinterpret_cast<const float4*>(sMf);   // [50]

    // Steady loop: warp-private 2-stage ring + dynamic chunk queue.
    int cnt = 0;
    while (c0 < nchunks) {
        int s = cnt & 1;
        unsigned phase = (cnt >> 1) & 1;
        mbar_wait(wmbar + s * 8, phase);

        int row = c0 * ROWS_W + lane;
        const float4* xr = ws + s * F4_W + lane * 25;
        float s0 = 0.0f, s1 = 0.0f;
        #pragma unroll
        for (int i = 0; i < 25; i++) {
            float4 v  = xr[i];
            float4 m0 = sM4[i];
            float4 m1 = sM4[25 + i];
            s0 = fmaf(v.x, m0.x, s0); s0 = fmaf(v.y, m0.y, s0);
            s0 = fmaf(v.z, m0.z, s0); s0 = fmaf(v.w, m0.w, s0);
            s1 = fmaf(v.x, m1.x, s1); s1 = fmaf(v.y, m1.y, s1);
            s1 = fmaf(v.z, m1.z, s1); s1 = fmaf(v.w, m1.w, s1);
        }
        if (row < batch) out[row] = make_float2(s0, s1);
        __syncwarp();                      // whole warp done reading stage s

        int cn = nchunks;                  // sentinel: queue exhausted
        if (c1 < nchunks) {                // keep pipeline only while alive
            cn = grab();
            if (cn < nchunks) issue(cn, s);
        }
        c0 = c1; c1 = cn; cnt++;
    }
}

extern "C" void kernel_launch(void* const* d_in, const int* in_sizes, int n_in,
                              void* d_out, int out_size) {
    const float* x        = (const float*)d_in[0];  // [BATCH, 100]
    const float* A_real   = (const float*)d_in[1];  // [2,10,10,100]
    const float* A_imag   = (const float*)d_in[2];  // [2,10,10,100]
    const float* psi_real = (const float*)d_in[3];  // [10]
    const float* psi_imag = (const float*)d_in[4];  // [10]

    int batch   = in_sizes[0] / 100;
    int nchunks = (batch + ROWS_W - 1) / ROWS_W;

    static void* ctrl_ptr = nullptr;
    static bool attr_done = false;
    if (!attr_done) {
        cudaFuncSetAttribute(fused_kernel,
                             cudaFuncAttributeMaxDynamicSharedMemorySize, SMEM_BYTES);
        cudaGetSymbolAddress(&ctrl_ptr, g_ctrl);
        attr_done = true;
    }

    // Reset counter/done/M each launch (graph-capturable memset node).
    cudaMemsetAsync(ctrl_ptr, 0, sizeof(Ctrl), 0);

    fused_kernel<<<NBLK, BLOCK_T, SMEM_BYTES>>>(x, A_real, A_imag,
                                                psi_real, psi_imag,
                                                reinterpret_cast<float2*>(d_out),
                                                batch, nchunks);
}

// round 12
// speedup vs baseline: 1.0902x; 1.0152x over previous
#include <cuda_runtime.h>
#include <cstdint>

#define WARPS_PB   8
#define BLOCK_T    256
#define ROWS_W     32                          // rows per warp-stage chunk
#define F4_W       (ROWS_W * 25)               // 800 float4 per stage
#define STAGES     2
#define SMEM_BYTES (WARPS_PB * STAGES * F4_W * 16)   // 204800 B -> 1 block/SM
#define NBLK       148

// Per-launch control block, zeroed by a cudaMemsetAsync graph node each launch.
struct Ctrl {
    int   done;         // count of finished M-blocks (target 20)
    int   pad0, pad1, pad2;
    float M[200];       // M[k*100 + a]
};
__device__ __align__(16) Ctrl g_ctrl;

__device__ __forceinline__ void mbar_wait(unsigned mbar, unsigned phase) {
    unsigned done;
    asm volatile("{\n\t.reg .pred p;\n\t"
                 "mbarrier.try_wait.parity.acquire.cta.shared::cta.b64 p, [%1], %2;\n\t"
                 "selp.b32 %0, 1, 0, p;\n\t}"
                 : "=r"(done) : "r"(mbar), "r"(phase) : "memory");
    while (!done) {
        asm volatile("{\n\t.reg .pred p;\n\t"
                     "mbarrier.try_wait.parity.acquire.cta.shared::cta.b64 p, [%1], %2, 0x989680;\n\t"
                     "selp.b32 %0, 1, 0, p;\n\t}"
                     : "=r"(done) : "r"(mbar), "r"(phase) : "memory");
    }
}

__global__ void __launch_bounds__(BLOCK_T, 1) fused_kernel(
    const float* __restrict__ x,
    const float* __restrict__ A_real,
    const float* __restrict__ A_imag,
    const float* __restrict__ psi_real,
    const float* __restrict__ psi_imag,
    float2* __restrict__ out,
    int batch, int nchunks)
{
    extern __shared__ __align__(128) float4 sx[];   // [WARPS_PB][STAGES][F4_W]
    __shared__ __align__(16) float sMf[200];
    __shared__ float spr[10], spi[10];
    __shared__ __align__(8) unsigned long long mbar_store[WARPS_PB * STAGES];

    int tid  = threadIdx.x;
    int wid  = tid >> 5;
    int lane = tid & 31;
    int bid  = blockIdx.x;

    unsigned mbar_base = (unsigned)__cvta_generic_to_shared(&mbar_store[0]);
    unsigned wmbar = mbar_base + (wid * STAGES) * 8;
    float4* ws = sx + (size_t)wid * (STAGES * F4_W);

    if (tid < WARPS_PB * STAGES)
        asm volatile("mbarrier.init.shared.b64 [%0], %1;"
                     :: "r"(mbar_base + tid * 8), "r"(1) : "memory");
    if (bid < 20 && tid < 10) { spr[tid] = psi_real[tid]; spi[tid] = psi_imag[tid]; }
    __syncthreads();

    int gwarp  = bid * WARPS_PB + wid;          // static interleave (R7)
    int stride = NBLK * WARPS_PB;               // 1184

    // Issue one 32-row chunk into warp-stage s (single bulk copy, lane 0).
    auto issue = [&](int chunk, int s) {
        if (lane == 0) {
            int rows = batch - chunk * ROWS_W;
            if (rows > ROWS_W) rows = ROWS_W;
            unsigned bytes = (unsigned)rows * 400u;
            unsigned mb = wmbar + s * 8;
            asm volatile("mbarrier.arrive.expect_tx.shared.b64 _, [%0], %1;"
                         :: "r"(mb), "r"(bytes) : "memory");
            unsigned dst = (unsigned)__cvta_generic_to_shared(ws + s * F4_W);
            const float* src = x + (size_t)chunk * (ROWS_W * 100);
            asm volatile("cp.async.bulk.shared::cta.global.mbarrier::complete_tx::bytes "
                         "[%0], [%1], %2, [%3];"
                         :: "r"(dst), "l"(src), "r"(bytes), "r"(mb) : "memory");
        }
    };

    // Prologue: every warp enqueues both stages first (~205KB/SM in flight).
    if (gwarp < nchunks)          issue(gwarp, 0);
    if (gwarp + stride < nchunks) issue(gwarp + stride, 1);

    // Blocks 0..19: compute the (k,i) partial of M (20 coalesced loads per
    // thread), hidden under the TMA flight. A is read once chip-wide (160KB).
    if (bid < 20 && tid < 100) {
        int k = bid / 10, i = bid - (bid / 10) * 10;
        int a = tid;
        int base = ((k * 10 + i) * 10) * 100 + a;
        float acc = 0.0f;
        #pragma unroll
        for (int j = 0; j < 10; j++) {
            float wr = spr[i] * spr[j] + spi[i] * spi[j];
            float wi = spr[i] * spi[j] - spi[i] * spr[j];
            acc = fmaf(wr,  __ldg(A_real + base + j * 100), acc);
            acc = fmaf(-wi, __ldg(A_imag + base + j * 100), acc);
        }
        atomicAdd(&g_ctrl.M[k * 100 + a], acc);
    }
    if (bid < 20) {
        __syncthreads();
        if (tid == 0) { __threadfence(); atomicAdd(&g_ctrl.done, 1); }
    }

    // All blocks: wait for M (shadowed by in-flight prologue copies).
    if (tid == 0) {
        while (atomicAdd(&g_ctrl.done, 0) < 20) __nanosleep(64);
    }
    __syncthreads();
    if (tid < 200) sMf[tid] = __ldcg(&g_ctrl.M[tid]);   // bypass L1
    __syncthreads();
    const float4* sM4 = reinterpret_cast<const float4*>(sMf);   // [50]

    // Steady loop (R7-identical): warp-private, static interleave, no atomics.
    int cnt = 0;
    for (int c = gwarp; c < nchunks; c += stride, cnt++) {
        int s = cnt & 1;
        unsigned phase = (cnt >> 1) & 1;
        mbar_wait(wmbar + s * 8, phase);

        int row = c * ROWS_W + lane;
        const float4* xr = ws + s * F4_W + lane * 25;
        float s0 = 0.0f, s1 = 0.0f;
        #pragma unroll
        for (int i = 0; i < 25; i++) {
            float4 v  = xr[i];
            float4 m0 = sM4[i];
            float4 m1 = sM4[25 + i];
            s0 = fmaf(v.x, m0.x, s0); s0 = fmaf(v.y, m0.y, s0);
            s0 = fmaf(v.z, m0.z, s0); s0 = fmaf(v.w, m0.w, s0);
            s1 = fmaf(v.x, m1.x, s1); s1 = fmaf(v.y, m1.y, s1);
            s1 = fmaf(v.z, m1.z, s1); s1 = fmaf(v.w, m1.w, s1);
        }
        if (row < batch) out[row] = make_float2(s0, s1);
        __syncwarp();                      // whole warp done reading stage s

        int cn = c + STAGES * stride;
        if (cn < nchunks) issue(cn, s);
    }
}

extern "C" void kernel_launch(void* const* d_in, const int* in_sizes, int n_in,
                              void* d_out, int out_size) {
    const float* x        = (const float*)d_in[0];  // [BATCH, 100]
    const float* A_real   = (const float*)d_in[1];  // [2,10,10,100]
    const float* A_imag   = (const float*)d_in[2];  // [2,10,10,100]
    const float* psi_real = (const float*)d_in[3];  // [10]
    const float* psi_imag = (const float*)d_in[4];  // [10]

    int batch   = in_sizes[0] / 100;
    int nchunks = (batch + ROWS_W - 1) / ROWS_W;

    static void* ctrl_ptr = nullptr;
    static bool attr_done = false;
    if (!attr_done) {
        cudaFuncSetAttribute(fused_kernel,
                             cudaFuncAttributeMaxDynamicSharedMemorySize, SMEM_BYTES);
        cudaGetSymbolAddress(&ctrl_ptr, g_ctrl);
        attr_done = true;
    }

    // Reset done-flag + M accumulators each launch (graph-capturable node).
    cudaMemsetAsync(ctrl_ptr, 0, sizeof(Ctrl), 0);

    fused_kernel<<<NBLK, BLOCK_T, SMEM_BYTES>>>(x, A_real, A_imag,
                                                psi_real, psi_imag,
                                                reinterpret_cast<float2*>(d_out),
                                                batch, nchunks);
}

// round 13
// speedup vs baseline: 1.1215x; 1.0287x over previous
#include <cuda_runtime.h>
#include <cstdint>

#define WARPS_PB   8
#define BLOCK_T    256
#define ROWS_W     32                          // rows per warp-stage chunk
#define F4_W       (ROWS_W * 25)               // 800 float4 per stage
#define STAGES     2
#define SMEM_BYTES (WARPS_PB * STAGES * F4_W * 16)   // 204800 B -> 1 block/SM
#define NBLK       148

// Per-launch control block, zeroed by a cudaMemsetAsync graph node each launch.
struct Ctrl {
    int   flags[20];    // one per producer block (k,i): load-only polling
    int   pad[12];
    float M[200];       // M[k*100 + a]
};
__device__ __align__(16) Ctrl g_ctrl;

__device__ __forceinline__ void mbar_wait(unsigned mbar, unsigned phase) {
    unsigned done;
    asm volatile("{\n\t.reg .pred p;\n\t"
                 "mbarrier.try_wait.parity.acquire.cta.shared::cta.b64 p, [%1], %2;\n\t"
                 "selp.b32 %0, 1, 0, p;\n\t}"
                 : "=r"(done) : "r"(mbar), "r"(phase) : "memory");
    while (!done) {
        asm volatile("{\n\t.reg .pred p;\n\t"
                     "mbarrier.try_wait.parity.acquire.cta.shared::cta.b64 p, [%1], %2, 0x989680;\n\t"
                     "selp.b32 %0, 1, 0, p;\n\t}"
                     : "=r"(done) : "r"(mbar), "r"(phase) : "memory");
    }
}

__global__ void __launch_bounds__(BLOCK_T, 1) fused_kernel(
    const float* __restrict__ x,
    const float* __restrict__ A_real,
    const float* __restrict__ A_imag,
    const float* __restrict__ psi_real,
    const float* __restrict__ psi_imag,
    float2* __restrict__ out,
    int batch, int nchunks)
{
    extern __shared__ __align__(128) float4 sx[];   // [WARPS_PB][STAGES][F4_W]
    __shared__ __align__(16) float sMf[200];
    __shared__ float spr[10], spi[10];
    __shared__ __align__(8) unsigned long long mbar_store[WARPS_PB * STAGES];

    int tid  = threadIdx.x;
    int wid  = tid >> 5;
    int lane = tid & 31;
    int bid  = blockIdx.x;

    unsigned mbar_base = (unsigned)__cvta_generic_to_shared(&mbar_store[0]);
    unsigned wmbar = mbar_base + (wid * STAGES) * 8;
    float4* ws = sx + (size_t)wid * (STAGES * F4_W);

    if (tid < WARPS_PB * STAGES)
        asm volatile("mbarrier.init.shared.b64 [%0], %1;"
                     :: "r"(mbar_base + tid * 8), "r"(1) : "memory");
    if (bid < 20 && tid < 10) { spr[tid] = psi_real[tid]; spi[tid] = psi_imag[tid]; }
    __syncthreads();

    int gwarp  = bid * WARPS_PB + wid;          // static interleave (R7)
    int stride = NBLK * WARPS_PB;               // 1184

    // Issue one 32-row chunk into warp-stage s (single bulk copy, lane 0).
    auto issue = [&](int chunk, int s) {
        if (lane == 0) {
            int rows = batch - chunk * ROWS_W;
            if (rows > ROWS_W) rows = ROWS_W;
            unsigned bytes = (unsigned)rows * 400u;
            unsigned mb = wmbar + s * 8;
            asm volatile("mbarrier.arrive.expect_tx.shared.b64 _, [%0], %1;"
                         :: "r"(mb), "r"(bytes) : "memory");
            unsigned dst = (unsigned)__cvta_generic_to_shared(ws + s * F4_W);
            const float* src = x + (size_t)chunk * (ROWS_W * 100);
            asm volatile("cp.async.bulk.shared::cta.global.mbarrier::complete_tx::bytes "
                         "[%0], [%1], %2, [%3];"
                         :: "r"(dst), "l"(src), "r"(bytes), "r"(mb) : "memory");
        }
    };

    // Prologue: every warp enqueues both stages first (~205KB/SM in flight).
    if (gwarp < nchunks)          issue(gwarp, 0);
    if (gwarp + stride < nchunks) issue(gwarp + stride, 1);

    // Blocks 0..19: compute the (k,i) partial of M (20 coalesced loads per
    // thread), hidden under the TMA flight. A is read once chip-wide (160KB).
    if (bid < 20) {
        if (tid < 100) {
            int k = bid / 10, i = bid - (bid / 10) * 10;
            int a = tid;
            int base = ((k * 10 + i) * 10) * 100 + a;
            float acc = 0.0f;
            #pragma unroll
            for (int j = 0; j < 10; j++) {
                float wr = spr[i] * spr[j] + spi[i] * spi[j];
                float wi = spr[i] * spi[j] - spi[i] * spr[j];
                acc = fmaf(wr,  __ldg(A_real + base + j * 100), acc);
                acc = fmaf(-wi, __ldg(A_imag + base + j * 100), acc);
            }
            atomicAdd(&g_ctrl.M[k * 100 + a], acc);
            __threadfence();                    // order my adds before the flag
        }
        __syncthreads();
        if (tid == 0) atomicExch(&g_ctrl.flags[bid], 1);
    }

    // All blocks: wait for all 20 producer flags. LOAD-ONLY polling on 20
    // distinct addresses -> no L2 atomic-ALU serialization, producers' flag
    // writes never queue behind readers. Shadowed by in-flight TMA copies.
    if (tid < 20) {
        const int* f = &g_ctrl.flags[tid];
        int v;
        do {
            asm volatile("ld.global.cg.b32 %0, [%1];" : "=r"(v) : "l"(f));
            if (!v) __nanosleep(64);
        } while (!v);
    }
    __syncthreads();
    __threadfence();
    if (tid < 200) sMf[tid] = __ldcg(&g_ctrl.M[tid]);   // bypass L1
    __syncthreads();
    const float4* sM4 = reinterpret_cast<const float4*>(sMf);   // [50]

    // Steady loop (R7-identical): warp-private, static interleave, no atomics.
    int cnt = 0;
    for (int c = gwarp; c < nchunks; c += stride, cnt++) {
        int s = cnt & 1;
        unsigned phase = (cnt >> 1) & 1;
        mbar_wait(wmbar + s * 8, phase);

        int row = c * ROWS_W + lane;
        const float4* xr = ws + s * F4_W + lane * 25;
        float s0 = 0.0f, s1 = 0.0f;
        #pragma unroll
        for (int i = 0; i < 25; i++) {
            float4 v  = xr[i];
            float4 m0 = sM4[i];
            float4 m1 = sM4[25 + i];
            s0 = fmaf(v.x, m0.x, s0); s0 = fmaf(v.y, m0.y, s0);
            s0 = fmaf(v.z, m0.z, s0); s0 = fmaf(v.w, m0.w, s0);
            s1 = fmaf(v.x, m1.x, s1); s1 = fmaf(v.y, m1.y, s1);
            s1 = fmaf(v.z, m1.z, s1); s1 = fmaf(v.w, m1.w, s1);
        }
        if (row < batch) out[row] = make_float2(s0, s1);
        __syncwarp();                      // whole warp done reading stage s

        int cn = c + STAGES * stride;
        if (cn < nchunks) issue(cn, s);
    }
}

extern "C" void kernel_launch(void* const* d_in, const int* in_sizes, int n_in,
                              void* d_out, int out_size) {
    const float* x        = (const float*)d_in[0];  // [BATCH, 100]
    const float* A_real   = (const float*)d_in[1];  // [2,10,10,100]
    const float* A_imag   = (const float*)d_in[2];  // [2,10,10,100]
    const float* psi_real = (const float*)d_in[3];  // [10]
    const float* psi_imag = (const float*)d_in[4];  // [10]

    int batch   = in_sizes[0] / 100;
    int nchunks = (batch + ROWS_W - 1) / ROWS_W;

    static void* ctrl_ptr = nullptr;
    static bool attr_done = false;
    if (!attr_done) {
        cudaFuncSetAttribute(fused_kernel,
                             cudaFuncAttributeMaxDynamicSharedMemorySize, SMEM_BYTES);
        cudaGetSymbolAddress(&ctrl_ptr, g_ctrl);
        attr_done = true;
    }

    // Reset flags + M accumulators each launch (graph-capturable node).
    cudaMemsetAsync(ctrl_ptr, 0, sizeof(Ctrl), 0);

    fused_kernel<<<NBLK, BLOCK_T, SMEM_BYTES>>>(x, A_real, A_imag,
                                                psi_real, psi_imag,
                                                reinterpret_cast<float2*>(d_out),
                                                batch, nchunks);
}